// round 1
// baseline (speedup 1.0000x reference)
#include <cuda_runtime.h>

#define B 8
#define TE 512
#define TD 256
#define H 256
#define JT 16

// Scratch (device globals: no allocations allowed)
__device__ float g_WeT[B * H * TE];  // [b][h][i]  = sum_k enc[b][i][k] * W[k][h]
__device__ float g_Uh [B * TD * H];  // [b][j][h]  = sum_k dec[b][j][k] * U[k][h]

__device__ __forceinline__ float tanh_fast(float x) {
    float y;
    asm("tanh.approx.f32 %0, %1;" : "=f"(y) : "f"(x));
    return y;
}

// ---------------------------------------------------------------------------
// GEMM1: g_WeT[b][h][i] = sum_k enc[b][i][k] * W[k][h]
// block tile: 64 h x 64 i, 256 threads, k-tile 16, 4x4 micro-tile
// ---------------------------------------------------------------------------
__global__ __launch_bounds__(256) void gemm_WeT(const float* __restrict__ enc,
                                                const float* __restrict__ W) {
    int b  = blockIdx.z;
    int h0 = blockIdx.y * 64;
    int i0 = blockIdx.x * 64;

    __shared__ float As[16][64];   // [k][h]  (direct from W)
    __shared__ float Bs[16][68];   // [k][i]  (transposed from enc), padded

    int t  = threadIdx.x;
    int tx = t & 15;       // -> i
    int ty = t >> 4;       // -> h
    float acc[4][4];
#pragma unroll
    for (int r = 0; r < 4; r++)
#pragma unroll
        for (int c = 0; c < 4; c++) acc[r][c] = 0.f;

    const float* encb = enc + (size_t)b * TE * H;

    for (int k0 = 0; k0 < H; k0 += 16) {
        {   // As: k = t/16, hq = t%16
            int k = t >> 4, hq = t & 15;
            float4 f = *(const float4*)&W[(k0 + k) * H + h0 + hq * 4];
            *(float4*)&As[k][hq * 4] = f;
        }
        {   // Bs: ii = t/4, kq = t%4 (transpose)
            int ii = t >> 2, kq = t & 3;
            float4 f = *(const float4*)&encb[(i0 + ii) * H + k0 + kq * 4];
            Bs[kq * 4 + 0][ii] = f.x;
            Bs[kq * 4 + 1][ii] = f.y;
            Bs[kq * 4 + 2][ii] = f.z;
            Bs[kq * 4 + 3][ii] = f.w;
        }
        __syncthreads();
#pragma unroll
        for (int kk = 0; kk < 16; kk++) {
            float4 a  = *(float4*)&As[kk][ty * 4];
            float4 bb = *(float4*)&Bs[kk][tx * 4];
            float av[4] = {a.x, a.y, a.z, a.w};
            float bv[4] = {bb.x, bb.y, bb.z, bb.w};
#pragma unroll
            for (int r = 0; r < 4; r++)
#pragma unroll
                for (int c = 0; c < 4; c++)
                    acc[r][c] = fmaf(av[r], bv[c], acc[r][c]);
        }
        __syncthreads();
    }

    float* out = g_WeT + (size_t)b * H * TE;
#pragma unroll
    for (int r = 0; r < 4; r++) {
        float4 o = make_float4(acc[r][0], acc[r][1], acc[r][2], acc[r][3]);
        *(float4*)&out[(h0 + ty * 4 + r) * TE + i0 + tx * 4] = o;
    }
}

// ---------------------------------------------------------------------------
// GEMM2: g_Uh[b][j][h] = sum_k dec[b][j][k] * U[k][h]
// block tile: 64 j x 64 h, 256 threads
// ---------------------------------------------------------------------------
__global__ __launch_bounds__(256) void gemm_Uh(const float* __restrict__ dec,
                                               const float* __restrict__ U) {
    int b  = blockIdx.z;
    int j0 = blockIdx.y * 64;
    int h0 = blockIdx.x * 64;

    __shared__ float Ds[16][68];   // [k][j]  (transposed from dec), padded
    __shared__ float Us_[16][64];  // [k][h]  (direct from U)

    int t  = threadIdx.x;
    int tx = t & 15;       // -> h
    int ty = t >> 4;       // -> j
    float acc[4][4];
#pragma unroll
    for (int r = 0; r < 4; r++)
#pragma unroll
        for (int c = 0; c < 4; c++) acc[r][c] = 0.f;

    const float* decb = dec + (size_t)b * TD * H;

    for (int k0 = 0; k0 < H; k0 += 16) {
        {   // Ds: jj = t/4, kq = t%4 (transpose)
            int jj = t >> 2, kq = t & 3;
            float4 f = *(const float4*)&decb[(j0 + jj) * H + k0 + kq * 4];
            Ds[kq * 4 + 0][jj] = f.x;
            Ds[kq * 4 + 1][jj] = f.y;
            Ds[kq * 4 + 2][jj] = f.z;
            Ds[kq * 4 + 3][jj] = f.w;
        }
        {   // Us_: k = t/16, hq = t%16
            int k = t >> 4, hq = t & 15;
            float4 f = *(const float4*)&U[(k0 + k) * H + h0 + hq * 4];
            *(float4*)&Us_[k][hq * 4] = f;
        }
        __syncthreads();
#pragma unroll
        for (int kk = 0; kk < 16; kk++) {
            float4 d  = *(float4*)&Ds[kk][ty * 4];
            float4 uu = *(float4*)&Us_[kk][tx * 4];
            float dv[4] = {d.x, d.y, d.z, d.w};
            float uv[4] = {uu.x, uu.y, uu.z, uu.w};
#pragma unroll
            for (int r = 0; r < 4; r++)
#pragma unroll
                for (int c = 0; c < 4; c++)
                    acc[r][c] = fmaf(dv[r], uv[c], acc[r][c]);
        }
        __syncthreads();
    }

    float* out = g_Uh + (size_t)b * TD * H;
#pragma unroll
    for (int r = 0; r < 4; r++) {
        float4 o = make_float4(acc[r][0], acc[r][1], acc[r][2], acc[r][3]);
        *(float4*)&out[(j0 + ty * 4 + r) * H + h0 + tx * 4] = o;
    }
}

// ---------------------------------------------------------------------------
// Fused energy + softmax + context.
// One block per (b, 16-row j tile). 512 threads (thread = encoder position i).
// sbuf is dual-purpose: phase 1 = Uh tile [JT][H], phase 2 = probs P [JT][TE].
// ---------------------------------------------------------------------------
__global__ __launch_bounds__(512) void attn_kernel(const float* __restrict__ enc,
                                                   const float* __restrict__ Va,
                                                   float* __restrict__ c_out,
                                                   float* __restrict__ e_out) {
    __shared__ float sbuf[JT * TE];       // 32 KB (Us view: JT*H = first 16 KB)
    __shared__ float Vs[H];
    __shared__ float red1[16][JT];        // 16 warps x JT partials
    __shared__ float m_s[JT];
    __shared__ float inv_s[JT];

    int t  = threadIdx.x;
    int b  = blockIdx.x >> 4;             // TD/JT = 16 tiles per batch
    int jt = blockIdx.x & 15;
    int j0 = jt * JT;

    // Load Uh tile into sbuf (as Us[jj][h]) and V into Vs
    for (int idx = t; idx < JT * H; idx += 512) {
        int jj = idx >> 8;                // /H
        int h  = idx & (H - 1);
        sbuf[jj * H + h] = g_Uh[((size_t)b * TD + j0 + jj) * H + h];
    }
    if (t < H) Vs[t] = Va[t];
    __syncthreads();

    // ---- Energy accumulation: acc[jj] = sum_h V[h]*tanh(WeT[b][h][i] + Us[jj][h])
    const int i = t;
    float acc[JT];
#pragma unroll
    for (int jj = 0; jj < JT; jj++) acc[jj] = 0.f;

    const float* wp = g_WeT + (size_t)b * H * TE + i;
#pragma unroll 2
    for (int h = 0; h < H; h++) {
        float w = wp[h * TE];
        float v = Vs[h];
#pragma unroll
        for (int jj = 0; jj < JT; jj++) {
            acc[jj] = fmaf(v, tanh_fast(w + sbuf[jj * H + h]), acc[jj]);
        }
    }

    // ---- Softmax over i (512 values spread across the 512 threads)
    int lane = t & 31, w = t >> 5;
#pragma unroll
    for (int jj = 0; jj < JT; jj++) {
        float m = acc[jj];
#pragma unroll
        for (int o = 16; o; o >>= 1) m = fmaxf(m, __shfl_xor_sync(0xffffffffu, m, o));
        if (lane == 0) red1[w][jj] = m;
    }
    __syncthreads();
    if (t < JT) {
        float m = red1[0][t];
#pragma unroll
        for (int ww = 1; ww < 16; ww++) m = fmaxf(m, red1[ww][t]);
        m_s[t] = m;
    }
    __syncthreads();

    float p[JT];
#pragma unroll
    for (int jj = 0; jj < JT; jj++) {
        p[jj] = __expf(acc[jj] - m_s[jj]);
        float s = p[jj];
#pragma unroll
        for (int o = 16; o; o >>= 1) s += __shfl_xor_sync(0xffffffffu, s, o);
        if (lane == 0) red1[w][jj] = s;
    }
    __syncthreads();
    if (t < JT) {
        float s = 0.f;
#pragma unroll
        for (int ww = 0; ww < 16; ww++) s += red1[ww][t];
        inv_s[t] = 1.0f / s;
    }
    __syncthreads();

    // Normalize, write e, stash probs in sbuf (overwrites dead Us region)
    float* e_base = e_out + ((size_t)b * TD + j0) * TE;
#pragma unroll
    for (int jj = 0; jj < JT; jj++) {
        float pn = p[jj] * inv_s[jj];
        sbuf[jj * TE + i]   = pn;
        e_base[jj * TE + i] = pn;
    }
    __syncthreads();

    // ---- Context: c[b][j0+jj][h] = sum_i P[jj][i] * enc[b][i][h]
    int h = t & (H - 1);
    int g = t >> 8;                 // 0: jj 0..7, 1: jj 8..15
    float cacc[8];
#pragma unroll
    for (int q = 0; q < 8; q++) cacc[q] = 0.f;

    const float* ep = enc + (size_t)b * TE * H + h;
    for (int i2 = 0; i2 < TE; i2 += 4) {
        float e0 = ep[(i2 + 0) * H];
        float e1 = ep[(i2 + 1) * H];
        float e2 = ep[(i2 + 2) * H];
        float e3 = ep[(i2 + 3) * H];
#pragma unroll
        for (int q = 0; q < 8; q++) {
            int jj = g * 8 + q;
            float4 p4 = *(float4*)&sbuf[jj * TE + i2];
            float a = cacc[q];
            a = fmaf(p4.x, e0, a);
            a = fmaf(p4.y, e1, a);
            a = fmaf(p4.z, e2, a);
            a = fmaf(p4.w, e3, a);
            cacc[q] = a;
        }
    }

    float* cb = c_out + ((size_t)b * TD + j0 + g * 8) * H + h;
#pragma unroll
    for (int q = 0; q < 8; q++) cb[q * H] = cacc[q];
}

// ---------------------------------------------------------------------------
extern "C" void kernel_launch(void* const* d_in, const int* in_sizes, int n_in,
                              void* d_out, int out_size) {
    const float* enc = (const float*)d_in[0];  // [B,TE,H]
    const float* dec = (const float*)d_in[1];  // [B,TD,H]
    const float* W   = (const float*)d_in[2];  // [H,H]
    const float* U   = (const float*)d_in[3];  // [H,H]
    const float* V   = (const float*)d_in[4];  // [H,1]

    float* c_out = (float*)d_out;              // [B,TD,H]
    float* e_out = (float*)d_out + B * TD * H; // [B,TD,TE]

    dim3 g1(TE / 64, H / 64, B);
    gemm_WeT<<<g1, 256>>>(enc, W);
    dim3 g2(H / 64, TD / 64, B);
    gemm_Uh<<<g2, 256>>>(dec, U);
    attn_kernel<<<B * (TD / JT), 512>>>(enc, V, c_out, e_out);
}

// round 2
// speedup vs baseline: 1.0828x; 1.0828x over previous
#include <cuda_runtime.h>

#define B 8
#define TE 512
#define TD 256
#define H 256

// Scratch (device globals: no allocations allowed)
__device__ float g_WeT[B * H * TE];  // [b][h][i]  = sum_k enc[b][i][k] * W[k][h]
__device__ float g_Uh [B * TD * H];  // [b][j][h]  = sum_k dec[b][j][k] * U[k][h]

__device__ __forceinline__ float tanh_fast(float x) {
    float y;
    asm("tanh.approx.f32 %0, %1;" : "=f"(y) : "f"(x));
    return y;
}

// ---- packed fp32x2 helpers (Blackwell FFMA2 path) ----
__device__ __forceinline__ unsigned long long pk2(float lo, float hi) {
    unsigned long long r;
    asm("mov.b64 %0, {%1, %2};" : "=l"(r) : "f"(lo), "f"(hi));
    return r;
}
__device__ __forceinline__ unsigned long long fma2(unsigned long long a,
                                                   unsigned long long b,
                                                   unsigned long long c) {
    unsigned long long d;
    asm("fma.rn.f32x2 %0, %1, %2, %3;" : "=l"(d) : "l"(a), "l"(b), "l"(c));
    return d;
}
__device__ __forceinline__ void upk2(unsigned long long v, float& lo, float& hi) {
    asm("mov.b64 {%0, %1}, %2;" : "=f"(lo), "=f"(hi) : "l"(v));
}

// 4x4 micro-tile step with packed math: rows from 'a' (pairs), cols from 'bb' (dup)
__device__ __forceinline__ void micro_fma2(unsigned long long acc2[2][4],
                                           float4 a, float4 bb) {
    unsigned long long pa0 = pk2(a.x, a.y);
    unsigned long long pa1 = pk2(a.z, a.w);
    unsigned long long pb0 = pk2(bb.x, bb.x);
    unsigned long long pb1 = pk2(bb.y, bb.y);
    unsigned long long pb2 = pk2(bb.z, bb.z);
    unsigned long long pb3 = pk2(bb.w, bb.w);
    acc2[0][0] = fma2(pa0, pb0, acc2[0][0]);
    acc2[0][1] = fma2(pa0, pb1, acc2[0][1]);
    acc2[0][2] = fma2(pa0, pb2, acc2[0][2]);
    acc2[0][3] = fma2(pa0, pb3, acc2[0][3]);
    acc2[1][0] = fma2(pa1, pb0, acc2[1][0]);
    acc2[1][1] = fma2(pa1, pb1, acc2[1][1]);
    acc2[1][2] = fma2(pa1, pb2, acc2[1][2]);
    acc2[1][3] = fma2(pa1, pb3, acc2[1][3]);
}

// ---------------------------------------------------------------------------
// Fused GEMM: blockIdx.x < 8  -> WeT path:  g_WeT[b][h][i] = enc[b][i][:] . W[:][h]
//             blockIdx.x >= 8 -> Uh  path:  g_Uh[b][j][h]  = dec[b][j][:] . U[:][h]
// 64x64 tiles, 256 threads, 4x4 micro (rows packed in pairs), k-tile 16.
// Grid: (12, 4, B) = 384 blocks.
// ---------------------------------------------------------------------------
__global__ __launch_bounds__(256) void gemm_fused(const float* __restrict__ enc,
                                                  const float* __restrict__ dec,
                                                  const float* __restrict__ W,
                                                  const float* __restrict__ U) {
    __shared__ float As[16][64];   // [k][row]  (weight-derived, direct)
    __shared__ float Bs[16][68];   // [k][col]  (activation, transposed), padded

    int b = blockIdx.z;
    int t = threadIdx.x;
    int tx = t & 15;       // -> col quad
    int ty = t >> 4;       // -> row quad

    unsigned long long acc2[2][4];
#pragma unroll
    for (int rp = 0; rp < 2; rp++)
#pragma unroll
        for (int c = 0; c < 4; c++) acc2[rp][c] = 0ull;

    if (blockIdx.x < 8) {
        // ---- WeT: rows = h (from W), cols = i (from enc, transposed) ----
        int i0 = blockIdx.x * 64;
        int h0 = blockIdx.y * 64;
        const float* encb = enc + (size_t)b * TE * H;

        for (int k0 = 0; k0 < H; k0 += 16) {
            {   int k = t >> 4, hq = t & 15;
                float4 f = *(const float4*)&W[(k0 + k) * H + h0 + hq * 4];
                *(float4*)&As[k][hq * 4] = f;
            }
            {   int ii = t >> 2, kq = t & 3;
                float4 f = *(const float4*)&encb[(i0 + ii) * H + k0 + kq * 4];
                Bs[kq * 4 + 0][ii] = f.x;
                Bs[kq * 4 + 1][ii] = f.y;
                Bs[kq * 4 + 2][ii] = f.z;
                Bs[kq * 4 + 3][ii] = f.w;
            }
            __syncthreads();
#pragma unroll
            for (int kk = 0; kk < 16; kk++) {
                float4 a  = *(float4*)&As[kk][ty * 4];
                float4 bb = *(float4*)&Bs[kk][tx * 4];
                micro_fma2(acc2, a, bb);
            }
            __syncthreads();
        }

        float o[4][4];
#pragma unroll
        for (int rp = 0; rp < 2; rp++)
#pragma unroll
            for (int c = 0; c < 4; c++)
                upk2(acc2[rp][c], o[2 * rp][c], o[2 * rp + 1][c]);

        float* out = g_WeT + (size_t)b * H * TE;
#pragma unroll
        for (int r = 0; r < 4; r++) {
            float4 v = make_float4(o[r][0], o[r][1], o[r][2], o[r][3]);
            *(float4*)&out[(h0 + ty * 4 + r) * TE + i0 + tx * 4] = v;
        }
    } else {
        // ---- Uh: rows = j (from dec, transposed), cols = h (from U) ----
        int j0 = (blockIdx.x - 8) * 64;
        int h0 = blockIdx.y * 64;
        const float* decb = dec + (size_t)b * TD * H;

        for (int k0 = 0; k0 < H; k0 += 16) {
            {   int k = t >> 4, hq = t & 15;
                float4 f = *(const float4*)&U[(k0 + k) * H + h0 + hq * 4];
                *(float4*)&As[k][hq * 4] = f;   // As = [k][h] cols
            }
            {   int jj = t >> 2, kq = t & 3;
                float4 f = *(const float4*)&decb[(j0 + jj) * H + k0 + kq * 4];
                Bs[kq * 4 + 0][jj] = f.x;
                Bs[kq * 4 + 1][jj] = f.y;
                Bs[kq * 4 + 2][jj] = f.z;
                Bs[kq * 4 + 3][jj] = f.w;       // Bs = [k][j] rows
            }
            __syncthreads();
#pragma unroll
            for (int kk = 0; kk < 16; kk++) {
                float4 a  = *(float4*)&Bs[kk][ty * 4];   // rows j (pairs)
                float4 bb = *(float4*)&As[kk][tx * 4];   // cols h (dup)
                micro_fma2(acc2, a, bb);
            }
            __syncthreads();
        }

        float o[4][4];
#pragma unroll
        for (int rp = 0; rp < 2; rp++)
#pragma unroll
            for (int c = 0; c < 4; c++)
                upk2(acc2[rp][c], o[2 * rp][c], o[2 * rp + 1][c]);

        float* out = g_Uh + (size_t)b * TD * H;
#pragma unroll
        for (int r = 0; r < 4; r++) {
            float4 v = make_float4(o[r][0], o[r][1], o[r][2], o[r][3]);
            *(float4*)&out[(j0 + ty * 4 + r) * H + h0 + tx * 4] = v;
        }
    }
}

// ---------------------------------------------------------------------------
// Energy + softmax. JT=2: one block per (b, 2 decoder rows) -> 1024 blocks.
// 512 threads, thread = encoder position i. Writes normalized probs to e_out.
// ---------------------------------------------------------------------------
__global__ __launch_bounds__(512) void energy_kernel(const float* __restrict__ Va,
                                                     float* __restrict__ e_out) {
    __shared__ float Us[2 * H];
    __shared__ float Vs[H];
    __shared__ float red[16][2];
    __shared__ float bmax[2];
    __shared__ float binv[2];

    int t  = threadIdx.x;
    int b  = blockIdx.x >> 7;            // TD/2 = 128 tiles per batch
    int j0 = (blockIdx.x & 127) * 2;

    // rows j0, j0+1 are contiguous in g_Uh -> one coalesced sweep
    Us[t] = g_Uh[((size_t)b * TD + j0) * H + t];
    if (t < H) Vs[t] = Va[t];
    __syncthreads();

    const int i = t;
    float acc0 = 0.f, acc1 = 0.f;
    const float* wp = g_WeT + (size_t)b * H * TE + i;
#pragma unroll 4
    for (int h = 0; h < H; h++) {
        float w = wp[h * TE];
        float v = Vs[h];
        acc0 = fmaf(v, tanh_fast(w + Us[h]),     acc0);
        acc1 = fmaf(v, tanh_fast(w + Us[H + h]), acc1);
    }

    // ---- softmax over i (512 values across 512 threads) ----
    int lane = t & 31, wrp = t >> 5;
    float m0 = acc0, m1 = acc1;
#pragma unroll
    for (int o = 16; o; o >>= 1) {
        m0 = fmaxf(m0, __shfl_xor_sync(0xffffffffu, m0, o));
        m1 = fmaxf(m1, __shfl_xor_sync(0xffffffffu, m1, o));
    }
    if (lane == 0) { red[wrp][0] = m0; red[wrp][1] = m1; }
    __syncthreads();
    if (t < 2) {
        float m = red[0][t];
#pragma unroll
        for (int w2 = 1; w2 < 16; w2++) m = fmaxf(m, red[w2][t]);
        bmax[t] = m;
    }
    __syncthreads();

    float p0 = __expf(acc0 - bmax[0]);
    float p1 = __expf(acc1 - bmax[1]);
    float s0 = p0, s1 = p1;
#pragma unroll
    for (int o = 16; o; o >>= 1) {
        s0 += __shfl_xor_sync(0xffffffffu, s0, o);
        s1 += __shfl_xor_sync(0xffffffffu, s1, o);
    }
    if (lane == 0) { red[wrp][0] = s0; red[wrp][1] = s1; }
    __syncthreads();
    if (t < 2) {
        float s = 0.f;
#pragma unroll
        for (int w2 = 0; w2 < 16; w2++) s += red[w2][t];
        binv[t] = 1.0f / s;
    }
    __syncthreads();

    float* e0 = e_out + ((size_t)b * TD + j0) * TE;
    e0[i]      = p0 * binv[0];
    e0[TE + i] = p1 * binv[1];
}

// ---------------------------------------------------------------------------
// Context GEMM: c[b] = P[b] @ enc[b]   ([TD x TE] x [TE x H])
// 64x64 tiles, 256 threads, 4x4 micro (packed), k-tile 16, K=512.
// Grid: (H/64, TD/64, B) = 128 blocks.
// ---------------------------------------------------------------------------
__global__ __launch_bounds__(256) void ctx_gemm(const float* __restrict__ P,
                                                const float* __restrict__ enc,
                                                float* __restrict__ c_out) {
    __shared__ float As[16][68];   // [k][j] transposed from P, padded
    __shared__ float Bs[16][64];   // [k][h] direct from enc

    int b  = blockIdx.z;
    int j0 = blockIdx.y * 64;
    int h0 = blockIdx.x * 64;
    int t  = threadIdx.x;
    int tx = t & 15;       // -> h quad
    int ty = t >> 4;       // -> j quad

    unsigned long long acc2[2][4];
#pragma unroll
    for (int rp = 0; rp < 2; rp++)
#pragma unroll
        for (int c = 0; c < 4; c++) acc2[rp][c] = 0ull;

    const float* Pb = P   + (size_t)b * TD * TE;
    const float* eb = enc + (size_t)b * TE * H;

    for (int k0 = 0; k0 < TE; k0 += 16) {
        {   int jj = t >> 2, kq = t & 3;
            float4 f = *(const float4*)&Pb[(j0 + jj) * TE + k0 + kq * 4];
            As[kq * 4 + 0][jj] = f.x;
            As[kq * 4 + 1][jj] = f.y;
            As[kq * 4 + 2][jj] = f.z;
            As[kq * 4 + 3][jj] = f.w;
        }
        {   int k = t >> 4, hq = t & 15;
            float4 f = *(const float4*)&eb[(k0 + k) * H + h0 + hq * 4];
            *(float4*)&Bs[k][hq * 4] = f;
        }
        __syncthreads();
#pragma unroll
        for (int kk = 0; kk < 16; kk++) {
            float4 a  = *(float4*)&As[kk][ty * 4];   // j rows (pairs)
            float4 bb = *(float4*)&Bs[kk][tx * 4];   // h cols (dup)
            micro_fma2(acc2, a, bb);
        }
        __syncthreads();
    }

    float o[4][4];
#pragma unroll
    for (int rp = 0; rp < 2; rp++)
#pragma unroll
        for (int c = 0; c < 4; c++)
            upk2(acc2[rp][c], o[2 * rp][c], o[2 * rp + 1][c]);

#pragma unroll
    for (int r = 0; r < 4; r++) {
        float4 v = make_float4(o[r][0], o[r][1], o[r][2], o[r][3]);
        *(float4*)&c_out[((size_t)b * TD + j0 + ty * 4 + r) * H + h0 + tx * 4] = v;
    }
}

// ---------------------------------------------------------------------------
extern "C" void kernel_launch(void* const* d_in, const int* in_sizes, int n_in,
                              void* d_out, int out_size) {
    const float* enc = (const float*)d_in[0];  // [B,TE,H]
    const float* dec = (const float*)d_in[1];  // [B,TD,H]
    const float* W   = (const float*)d_in[2];  // [H,H]
    const float* U   = (const float*)d_in[3];  // [H,H]
    const float* V   = (const float*)d_in[4];  // [H,1]

    float* c_out = (float*)d_out;              // [B,TD,H]
    float* e_out = (float*)d_out + B * TD * H; // [B,TD,TE]

    dim3 gg(12, 4, B);                         // 8 i-tiles (WeT) + 4 j-tiles (Uh)
    gemm_fused<<<gg, 256>>>(enc, dec, W, U);
    energy_kernel<<<B * (TD / 2), 512>>>(V, e_out);
    dim3 gc(H / 64, TD / 64, B);
    ctx_gemm<<<gc, 256>>>(e_out, enc, c_out);
}